// round 2
// baseline (speedup 1.0000x reference)
#include <cuda_runtime.h>
#include <math.h>

#define BATCH 32
#define NTOK  3136
#define DIM   384
#define HEADS 8
#define CH    48

// Scratch (device globals; no allocations allowed)
__device__ float g_S  [(size_t)BATCH * DIM * DIM];       // per-batch Gram X^T X
__device__ float g_Aqk[(size_t)BATCH * 2 * DIM * DIM];   // [Wq;Wk] @ S  (768 x 384 per batch)
__device__ float g_M  [(size_t)BATCH * DIM * DIM];       // attn-combined V weights
__device__ float g_P  [(size_t)BATCH * DIM * DIM];       // proj_w @ M

// ---------------------------------------------------------------------------
// Kernel A: S_b = X_b^T X_b    (M=N=384, K=3136, batched over 32)
// Symmetric: compute only upper-triangle 64x64 tiles (21 of 36), mirror with
// transposed float4 stores. The mirrored sums are bitwise identical (same
// k-order, commuted multiply), so the diagonal-tile double-write is benign.
// ---------------------------------------------------------------------------
__global__ __launch_bounds__(256) void k_syrk(const float* __restrict__ x) {
    const int b = blockIdx.z;
    // map blockIdx.x in [0,21) -> (ti, tj) with ti <= tj
    int idx = blockIdx.x;
    int ti = 0;
    while (idx >= 6 - ti) { idx -= 6 - ti; ti++; }
    const int tj = ti + idx;
    const int i0 = ti * 64;
    const int j0 = tj * 64;
    const float* X = x + (size_t)b * NTOK * DIM;

    __shared__ __align__(16) float sA[16][64];
    __shared__ __align__(16) float sB[16][64];

    const int t  = threadIdx.x;
    const int tx = t & 15, ty = t >> 4;
    const int lr = t >> 4, lc = (t & 15) * 4;

    float acc[4][4] = {};
    for (int k0 = 0; k0 < NTOK; k0 += 16) {
        float4 va = *(const float4*)&X[(size_t)(k0 + lr) * DIM + i0 + lc];
        float4 vb = *(const float4*)&X[(size_t)(k0 + lr) * DIM + j0 + lc];
        __syncthreads();
        *(float4*)&sA[lr][lc] = va;
        *(float4*)&sB[lr][lc] = vb;
        __syncthreads();
#pragma unroll
        for (int kk = 0; kk < 16; kk++) {
            float4 a4 = *(const float4*)&sA[kk][ty * 4];
            float4 b4 = *(const float4*)&sB[kk][tx * 4];
            float a[4] = {a4.x, a4.y, a4.z, a4.w};
            float bb[4] = {b4.x, b4.y, b4.z, b4.w};
#pragma unroll
            for (int r = 0; r < 4; r++)
#pragma unroll
                for (int c = 0; c < 4; c++) acc[r][c] += a[r] * bb[c];
        }
    }
    float* Sb = g_S + (size_t)b * DIM * DIM;
#pragma unroll
    for (int r = 0; r < 4; r++) {
        float4 o = {acc[r][0], acc[r][1], acc[r][2], acc[r][3]};
        *(float4*)&Sb[(size_t)(i0 + ty * 4 + r) * DIM + j0 + tx * 4] = o;
    }
    if (ti != tj) {
#pragma unroll
        for (int c = 0; c < 4; c++) {
            float4 o = {acc[0][c], acc[1][c], acc[2][c], acc[3][c]};
            *(float4*)&Sb[(size_t)(j0 + tx * 4 + c) * DIM + i0 + ty * 4] = o;
        }
    }
}

// ---------------------------------------------------------------------------
// Kernel NN: C[b][m][n] = sum_k A[m][k] * Bsrc[b][k][n]
// A shared across batches (row-major, K contiguous). Used for:
//   Aqk = qkv_w[0:768] @ S_b   (M=768)
//   P   = proj_w      @ M_b    (M=384)
// ---------------------------------------------------------------------------
__global__ __launch_bounds__(256) void k_gemm_nn(const float* __restrict__ A,
                                                 const float* __restrict__ Bsrc,
                                                 float* __restrict__ Cdst, int M) {
    const int b  = blockIdx.z;
    const int m0 = blockIdx.y * 64;
    const int n0 = blockIdx.x * 64;
    const float* Bb = Bsrc + (size_t)b * DIM * DIM;
    float* Cb = Cdst + (size_t)b * M * DIM;

    __shared__ __align__(16) float sA[16][68];   // [k][m], transposed store
    __shared__ __align__(16) float sB[16][64];   // [k][n], direct store

    const int t  = threadIdx.x;
    const int tx = t & 15, ty = t >> 4;
    const int amm = t >> 2, ak4 = (t & 3) * 4;   // A-tile loader coords
    const int bkk = t >> 4, bn4 = (t & 15) * 4;  // B-tile loader coords

    float acc[4][4] = {};
    for (int k0 = 0; k0 < DIM; k0 += 16) {
        float4 va = *(const float4*)&A[(size_t)(m0 + amm) * DIM + k0 + ak4];
        float4 vb = *(const float4*)&Bb[(size_t)(k0 + bkk) * DIM + n0 + bn4];
        __syncthreads();
        sA[ak4 + 0][amm] = va.x;
        sA[ak4 + 1][amm] = va.y;
        sA[ak4 + 2][amm] = va.z;
        sA[ak4 + 3][amm] = va.w;
        *(float4*)&sB[bkk][bn4] = vb;
        __syncthreads();
#pragma unroll
        for (int kk = 0; kk < 16; kk++) {
            float4 a4 = *(const float4*)&sA[kk][ty * 4];
            float4 b4 = *(const float4*)&sB[kk][tx * 4];
            float a[4] = {a4.x, a4.y, a4.z, a4.w};
            float bb[4] = {b4.x, b4.y, b4.z, b4.w};
#pragma unroll
            for (int r = 0; r < 4; r++)
#pragma unroll
                for (int c = 0; c < 4; c++) acc[r][c] += a[r] * bb[c];
        }
    }
#pragma unroll
    for (int r = 0; r < 4; r++) {
        float4 o = {acc[r][0], acc[r][1], acc[r][2], acc[r][3]};
        *(float4*)&Cb[(size_t)(m0 + ty * 4 + r) * DIM + n0 + tx * 4] = o;
    }
}

// ---------------------------------------------------------------------------
// Kernel NT: C[b][m][n] = sum_k A[b][m][k] * Bt[b][n][k] + bias[n]
// Used for: out = X_b @ P_b^T + proj_b   (M=3136, N=384, K=384)
// ---------------------------------------------------------------------------
__global__ __launch_bounds__(256) void k_gemm_nt(const float* __restrict__ A,
                                                 const float* __restrict__ Bt,
                                                 const float* __restrict__ bias,
                                                 float* __restrict__ Cdst) {
    const int b  = blockIdx.z;
    const int m0 = blockIdx.y * 64;
    const int n0 = blockIdx.x * 64;
    const float* Ab = A  + (size_t)b * NTOK * DIM;
    const float* Bb = Bt + (size_t)b * DIM * DIM;
    float* Cb = Cdst + (size_t)b * NTOK * DIM;

    __shared__ __align__(16) float sA[16][68];   // [k][m]
    __shared__ __align__(16) float sB[16][68];   // [k][n]

    const int t  = threadIdx.x;
    const int tx = t & 15, ty = t >> 4;
    const int rr = t >> 2, k4 = (t & 3) * 4;

    float acc[4][4] = {};
    for (int k0 = 0; k0 < DIM; k0 += 16) {
        float4 va = *(const float4*)&Ab[(size_t)(m0 + rr) * DIM + k0 + k4];
        float4 vb = *(const float4*)&Bb[(size_t)(n0 + rr) * DIM + k0 + k4];
        __syncthreads();
        sA[k4 + 0][rr] = va.x;
        sA[k4 + 1][rr] = va.y;
        sA[k4 + 2][rr] = va.z;
        sA[k4 + 3][rr] = va.w;
        sB[k4 + 0][rr] = vb.x;
        sB[k4 + 1][rr] = vb.y;
        sB[k4 + 2][rr] = vb.z;
        sB[k4 + 3][rr] = vb.w;
        __syncthreads();
#pragma unroll
        for (int kk = 0; kk < 16; kk++) {
            float4 a4 = *(const float4*)&sA[kk][ty * 4];
            float4 b4 = *(const float4*)&sB[kk][tx * 4];
            float a[4] = {a4.x, a4.y, a4.z, a4.w};
            float bb[4] = {b4.x, b4.y, b4.z, b4.w};
#pragma unroll
            for (int r = 0; r < 4; r++)
#pragma unroll
                for (int c = 0; c < 4; c++) acc[r][c] += a[r] * bb[c];
        }
    }
    float4 bi = *(const float4*)&bias[n0 + tx * 4];
#pragma unroll
    for (int r = 0; r < 4; r++) {
        float4 o = {acc[r][0] + bi.x, acc[r][1] + bi.y,
                    acc[r][2] + bi.z, acc[r][3] + bi.w};
        *(float4*)&Cb[(size_t)(m0 + ty * 4 + r) * DIM + n0 + tx * 4] = o;
    }
}

// ---------------------------------------------------------------------------
// Kernel C: per (b,h): norms, Gram, softmax, M = attn @ Wv_h
// ---------------------------------------------------------------------------
__global__ __launch_bounds__(256) void k_attn(const float* __restrict__ qkv_w,
                                              const float* __restrict__ temperature) {
    const int b = blockIdx.y;
    const int h = blockIdx.x;
    const int t = threadIdx.x;
    const int lane = t & 31, w = t >> 5;
    const int ty = t >> 4, tx = t & 15;

    __shared__ __align__(16) float sh0[64 * 50];
    __shared__ __align__(16) float sh1[64 * 50];
    __shared__ float sG[48 * 48];
    __shared__ float s_nq[48], s_nk[48];

    const float* Aq = g_Aqk + ((size_t)b * 768 + h * CH) * DIM;
    const float* Ak = Aq + (size_t)DIM * DIM;
    const float* Wq = qkv_w + (size_t)(h * CH) * DIM;
    const float* Wk = qkv_w + (size_t)(DIM + h * CH) * DIM;
    const float* Wv = qkv_w + (size_t)(2 * DIM + h * CH) * DIM;

    // --- norms: nq[c] = sqrt(Aq[c] . Wq[c]), nk likewise. 8 warps x 6 rows.
    for (int i = 0; i < 6; i++) {
        int r = w * 6 + i;
        float s = 0.f, s2 = 0.f;
        for (int k = lane; k < DIM; k += 32) {
            s  += Aq[r * DIM + k] * Wq[r * DIM + k];
            s2 += Ak[r * DIM + k] * Wk[r * DIM + k];
        }
#pragma unroll
        for (int o = 16; o; o >>= 1) {
            s  += __shfl_xor_sync(0xffffffffu, s, o);
            s2 += __shfl_xor_sync(0xffffffffu, s2, o);
        }
        if (lane == 0) { s_nq[r] = sqrtf(s); s_nk[r] = sqrtf(s2); }
    }

    // --- G = Aq @ Wk^T  (48x48, K=384), chunked K=64, transposed smem tiles
    float acc[3][3] = {};
    for (int k0 = 0; k0 < DIM; k0 += 64) {
        __syncthreads();
#pragma unroll
        for (int i = 0; i < 3; i++) {
            int idx = t + i * 256;
            int row = idx >> 4, c4 = (idx & 15) * 4;
            float4 va = *(const float4*)&Aq[(size_t)row * DIM + k0 + c4];
            float4 vb = *(const float4*)&Wk[(size_t)row * DIM + k0 + c4];
            sh0[(c4 + 0) * 50 + row] = va.x;  sh0[(c4 + 1) * 50 + row] = va.y;
            sh0[(c4 + 2) * 50 + row] = va.z;  sh0[(c4 + 3) * 50 + row] = va.w;
            sh1[(c4 + 0) * 50 + row] = vb.x;  sh1[(c4 + 1) * 50 + row] = vb.y;
            sh1[(c4 + 2) * 50 + row] = vb.z;  sh1[(c4 + 3) * 50 + row] = vb.w;
        }
        __syncthreads();
#pragma unroll 8
        for (int kk = 0; kk < 64; kk++) {
            float a0 = sh0[kk * 50 + ty * 3 + 0];
            float a1 = sh0[kk * 50 + ty * 3 + 1];
            float a2 = sh0[kk * 50 + ty * 3 + 2];
            float b0 = sh1[kk * 50 + tx * 3 + 0];
            float b1 = sh1[kk * 50 + tx * 3 + 1];
            float b2 = sh1[kk * 50 + tx * 3 + 2];
            acc[0][0] += a0 * b0; acc[0][1] += a0 * b1; acc[0][2] += a0 * b2;
            acc[1][0] += a1 * b0; acc[1][1] += a1 * b1; acc[1][2] += a1 * b2;
            acc[2][0] += a2 * b0; acc[2][1] += a2 * b1; acc[2][2] += a2 * b2;
        }
    }
#pragma unroll
    for (int i = 0; i < 3; i++)
#pragma unroll
        for (int j = 0; j < 3; j++)
            sG[(ty * 3 + i) * 48 + tx * 3 + j] = acc[i][j];
    __syncthreads();

    // --- softmax over d with normalization + temperature
    const float temp = temperature[h];
    const float EPS = 1e-12f;
    for (int i = 0; i < 6; i++) {
        int r = w * 6 + i;
        float inq = 1.f / fmaxf(s_nq[r], EPS);
        int d0 = lane, d1 = lane + 32;
        float l0 = sG[r * 48 + d0] * inq / fmaxf(s_nk[d0], EPS) * temp;
        float l1 = (d1 < 48) ? sG[r * 48 + d1] * inq / fmaxf(s_nk[d1], EPS) * temp
                             : -1e30f;
        float m = fmaxf(l0, l1);
#pragma unroll
        for (int o = 16; o; o >>= 1) m = fmaxf(m, __shfl_xor_sync(0xffffffffu, m, o));
        float e0 = expf(l0 - m);
        float e1 = (d1 < 48) ? expf(l1 - m) : 0.f;
        float s = e0 + e1;
#pragma unroll
        for (int o = 16; o; o >>= 1) s += __shfl_xor_sync(0xffffffffu, s, o);
        float inv = 1.f / s;
        sG[r * 48 + d0] = e0 * inv;
        if (d1 < 48) sG[r * 48 + d1] = e1 * inv;
    }
    __syncthreads();

    // --- M[c][j] = sum_d attn[c][d] * Wv[d][j]  (48x384), j-chunked 64
    float* Mout = g_M + ((size_t)b * DIM + h * CH) * DIM;
    for (int j0 = 0; j0 < DIM; j0 += 64) {
        __syncthreads();
#pragma unroll
        for (int i = 0; i < 3; i++) {
            int idx = t + i * 256;
            int row = idx >> 4, c4 = (idx & 15) * 4;
            *(float4*)&sh0[row * 64 + c4] =
                *(const float4*)&Wv[(size_t)row * DIM + j0 + c4];
        }
        __syncthreads();
        float4 a4[3];
#pragma unroll
        for (int i = 0; i < 3; i++) a4[i] = make_float4(0.f, 0.f, 0.f, 0.f);
        for (int d = 0; d < 48; d++) {
            float4 v = *(const float4*)&sh0[d * 64 + tx * 4];
#pragma unroll
            for (int i = 0; i < 3; i++) {
                float a = sG[(ty * 3 + i) * 48 + d];
                a4[i].x += a * v.x; a4[i].y += a * v.y;
                a4[i].z += a * v.z; a4[i].w += a * v.w;
            }
        }
#pragma unroll
        for (int i = 0; i < 3; i++)
            *(float4*)&Mout[(size_t)(ty * 3 + i) * DIM + j0 + tx * 4] = a4[i];
    }
}

// ---------------------------------------------------------------------------
extern "C" void kernel_launch(void* const* d_in, const int* in_sizes, int n_in,
                              void* d_out, int out_size) {
    const float *x = nullptr, *qkv_w = nullptr, *temp = nullptr,
                *proj_w = nullptr, *proj_b = nullptr;
    for (int i = 0; i < n_in; i++) {
        switch (in_sizes[i]) {
            case BATCH * NTOK * DIM: x      = (const float*)d_in[i]; break;
            case 3 * DIM * DIM:      qkv_w  = (const float*)d_in[i]; break;
            case HEADS:              temp   = (const float*)d_in[i]; break;
            case DIM * DIM:          proj_w = (const float*)d_in[i]; break;
            case DIM:                proj_b = (const float*)d_in[i]; break;
        }
    }
    float* out = (float*)d_out;

    float *pS, *pAqk, *pM, *pP;
    cudaGetSymbolAddress((void**)&pS,   g_S);
    cudaGetSymbolAddress((void**)&pAqk, g_Aqk);
    cudaGetSymbolAddress((void**)&pM,   g_M);
    cudaGetSymbolAddress((void**)&pP,   g_P);

    dim3 blk(256);
    // 1. S_b = X^T X  (upper-triangle tiles only: 21 per batch)
    k_syrk<<<dim3(21, 1, BATCH), blk>>>(x);
    // 2. Aqk = [Wq; Wk] @ S_b   (M = 768)
    k_gemm_nn<<<dim3(6, 12, BATCH), blk>>>(qkv_w, pS, pAqk, 768);
    // 3. attention core -> M_b
    k_attn<<<dim3(HEADS, BATCH), blk>>>(qkv_w, temp);
    // 4. P_b = proj_w @ M_b     (M = 384)
    k_gemm_nn<<<dim3(6, 6, BATCH), blk>>>(proj_w, pM, pP, DIM);
    // 5. out = X_b @ P_b^T + bias
    k_gemm_nt<<<dim3(6, 49, BATCH), blk>>>(x, pP, proj_b, out);
}

// round 3
// speedup vs baseline: 1.0527x; 1.0527x over previous
#include <cuda_runtime.h>
#include <math.h>

#define BATCH 32
#define NTOK  3136
#define DIM   384
#define HEADS 8
#define CH    48

// Scratch (device globals; no allocations allowed)
__device__ float g_S  [(size_t)BATCH * DIM * DIM];       // per-batch Gram X^T X
__device__ float g_Aqk[(size_t)BATCH * 2 * DIM * DIM];   // [Wq;Wk] @ S  (768 x 384 per batch)
__device__ float g_M  [(size_t)BATCH * DIM * DIM];       // attn-combined V weights
__device__ float g_P  [(size_t)BATCH * DIM * DIM];       // proj_w @ M

// ---------------------------------------------------------------------------
// Kernel A: S_b = X_b^T X_b    (M=N=384, K=3136, batched over 32)
// Symmetric: compute only upper-triangle 64x64 tiles (21 of 36), mirror with
// transposed float4 stores. The mirrored sums are bitwise identical (same
// k-order, commuted multiply), so the diagonal-tile double-write is benign.
// ---------------------------------------------------------------------------
__global__ __launch_bounds__(256) void k_syrk(const float* __restrict__ x) {
    const int b = blockIdx.z;
    // map blockIdx.x in [0,21) -> (ti, tj) with ti <= tj
    int idx = blockIdx.x;
    int ti = 0;
    while (idx >= 6 - ti) { idx -= 6 - ti; ti++; }
    const int tj = ti + idx;
    const int i0 = ti * 64;
    const int j0 = tj * 64;
    const float* X = x + (size_t)b * NTOK * DIM;

    __shared__ __align__(16) float sA[16][64];
    __shared__ __align__(16) float sB[16][64];

    const int t  = threadIdx.x;
    const int tx = t & 15, ty = t >> 4;
    const int lr = t >> 4, lc = (t & 15) * 4;

    float acc[4][4] = {};
    for (int k0 = 0; k0 < NTOK; k0 += 16) {
        float4 va = *(const float4*)&X[(size_t)(k0 + lr) * DIM + i0 + lc];
        float4 vb = *(const float4*)&X[(size_t)(k0 + lr) * DIM + j0 + lc];
        __syncthreads();
        *(float4*)&sA[lr][lc] = va;
        *(float4*)&sB[lr][lc] = vb;
        __syncthreads();
#pragma unroll
        for (int kk = 0; kk < 16; kk++) {
            float4 a4 = *(const float4*)&sA[kk][ty * 4];
            float4 b4 = *(const float4*)&sB[kk][tx * 4];
            float a[4] = {a4.x, a4.y, a4.z, a4.w};
            float bb[4] = {b4.x, b4.y, b4.z, b4.w};
#pragma unroll
            for (int r = 0; r < 4; r++)
#pragma unroll
                for (int c = 0; c < 4; c++) acc[r][c] += a[r] * bb[c];
        }
    }
    float* Sb = g_S + (size_t)b * DIM * DIM;
#pragma unroll
    for (int r = 0; r < 4; r++) {
        float4 o = {acc[r][0], acc[r][1], acc[r][2], acc[r][3]};
        *(float4*)&Sb[(size_t)(i0 + ty * 4 + r) * DIM + j0 + tx * 4] = o;
    }
    if (ti != tj) {
#pragma unroll
        for (int c = 0; c < 4; c++) {
            float4 o = {acc[0][c], acc[1][c], acc[2][c], acc[3][c]};
            *(float4*)&Sb[(size_t)(j0 + tx * 4 + c) * DIM + i0 + ty * 4] = o;
        }
    }
}

// ---------------------------------------------------------------------------
// Kernel NN: C[b][m][n] = sum_k A[m][k] * Bsrc[b][k][n]
// A shared across batches (row-major, K contiguous). Used for:
//   Aqk = qkv_w[0:768] @ S_b   (M=768)
//   P   = proj_w      @ M_b    (M=384)
// ---------------------------------------------------------------------------
__global__ __launch_bounds__(256) void k_gemm_nn(const float* __restrict__ A,
                                                 const float* __restrict__ Bsrc,
                                                 float* __restrict__ Cdst, int M) {
    const int b  = blockIdx.z;
    const int m0 = blockIdx.y * 64;
    const int n0 = blockIdx.x * 64;
    const float* Bb = Bsrc + (size_t)b * DIM * DIM;
    float* Cb = Cdst + (size_t)b * M * DIM;

    __shared__ __align__(16) float sA[16][68];   // [k][m], transposed store
    __shared__ __align__(16) float sB[16][64];   // [k][n], direct store

    const int t  = threadIdx.x;
    const int tx = t & 15, ty = t >> 4;
    const int amm = t >> 2, ak4 = (t & 3) * 4;   // A-tile loader coords
    const int bkk = t >> 4, bn4 = (t & 15) * 4;  // B-tile loader coords

    float acc[4][4] = {};
    for (int k0 = 0; k0 < DIM; k0 += 16) {
        float4 va = *(const float4*)&A[(size_t)(m0 + amm) * DIM + k0 + ak4];
        float4 vb = *(const float4*)&Bb[(size_t)(k0 + bkk) * DIM + n0 + bn4];
        __syncthreads();
        sA[ak4 + 0][amm] = va.x;
        sA[ak4 + 1][amm] = va.y;
        sA[ak4 + 2][amm] = va.z;
        sA[ak4 + 3][amm] = va.w;
        *(float4*)&sB[bkk][bn4] = vb;
        __syncthreads();
#pragma unroll
        for (int kk = 0; kk < 16; kk++) {
            float4 a4 = *(const float4*)&sA[kk][ty * 4];
            float4 b4 = *(const float4*)&sB[kk][tx * 4];
            float a[4] = {a4.x, a4.y, a4.z, a4.w};
            float bb[4] = {b4.x, b4.y, b4.z, b4.w};
#pragma unroll
            for (int r = 0; r < 4; r++)
#pragma unroll
                for (int c = 0; c < 4; c++) acc[r][c] += a[r] * bb[c];
        }
    }
#pragma unroll
    for (int r = 0; r < 4; r++) {
        float4 o = {acc[r][0], acc[r][1], acc[r][2], acc[r][3]};
        *(float4*)&Cb[(size_t)(m0 + ty * 4 + r) * DIM + n0 + tx * 4] = o;
    }
}

// ---------------------------------------------------------------------------
// Kernel NT: C[b][m][n] = sum_k A[b][m][k] * Bt[b][n][k] + bias[n]
// Used for: out = X_b @ P_b^T + proj_b   (M=3136, N=384, K=384)
// ---------------------------------------------------------------------------
__global__ __launch_bounds__(256) void k_gemm_nt(const float* __restrict__ A,
                                                 const float* __restrict__ Bt,
                                                 const float* __restrict__ bias,
                                                 float* __restrict__ Cdst) {
    const int b  = blockIdx.z;
    const int m0 = blockIdx.y * 64;
    const int n0 = blockIdx.x * 64;
    const float* Ab = A  + (size_t)b * NTOK * DIM;
    const float* Bb = Bt + (size_t)b * DIM * DIM;
    float* Cb = Cdst + (size_t)b * NTOK * DIM;

    __shared__ __align__(16) float sA[16][68];   // [k][m]
    __shared__ __align__(16) float sB[16][68];   // [k][n]

    const int t  = threadIdx.x;
    const int tx = t & 15, ty = t >> 4;
    const int rr = t >> 2, k4 = (t & 3) * 4;

    float acc[4][4] = {};
    for (int k0 = 0; k0 < DIM; k0 += 16) {
        float4 va = *(const float4*)&Ab[(size_t)(m0 + rr) * DIM + k0 + k4];
        float4 vb = *(const float4*)&Bb[(size_t)(n0 + rr) * DIM + k0 + k4];
        __syncthreads();
        sA[k4 + 0][rr] = va.x;
        sA[k4 + 1][rr] = va.y;
        sA[k4 + 2][rr] = va.z;
        sA[k4 + 3][rr] = va.w;
        sB[k4 + 0][rr] = vb.x;
        sB[k4 + 1][rr] = vb.y;
        sB[k4 + 2][rr] = vb.z;
        sB[k4 + 3][rr] = vb.w;
        __syncthreads();
#pragma unroll
        for (int kk = 0; kk < 16; kk++) {
            float4 a4 = *(const float4*)&sA[kk][ty * 4];
            float4 b4 = *(const float4*)&sB[kk][tx * 4];
            float a[4] = {a4.x, a4.y, a4.z, a4.w};
            float bb[4] = {b4.x, b4.y, b4.z, b4.w};
#pragma unroll
            for (int r = 0; r < 4; r++)
#pragma unroll
                for (int c = 0; c < 4; c++) acc[r][c] += a[r] * bb[c];
        }
    }
    float4 bi = *(const float4*)&bias[n0 + tx * 4];
#pragma unroll
    for (int r = 0; r < 4; r++) {
        float4 o = {acc[r][0] + bi.x, acc[r][1] + bi.y,
                    acc[r][2] + bi.z, acc[r][3] + bi.w};
        *(float4*)&Cb[(size_t)(m0 + ty * 4 + r) * DIM + n0 + tx * 4] = o;
    }
}

// ---------------------------------------------------------------------------
// Kernel C: per (b,h): norms, Gram, softmax, M = attn @ Wv_h
// ---------------------------------------------------------------------------
__global__ __launch_bounds__(256) void k_attn(const float* __restrict__ qkv_w,
                                              const float* __restrict__ temperature) {
    const int b = blockIdx.y;
    const int h = blockIdx.x;
    const int t = threadIdx.x;
    const int lane = t & 31, w = t >> 5;
    const int ty = t >> 4, tx = t & 15;

    __shared__ __align__(16) float sh0[64 * 50];
    __shared__ __align__(16) float sh1[64 * 50];
    __shared__ float sG[48 * 48];
    __shared__ float s_nq[48], s_nk[48];

    const float* Aq = g_Aqk + ((size_t)b * 768 + h * CH) * DIM;
    const float* Ak = Aq + (size_t)DIM * DIM;
    const float* Wq = qkv_w + (size_t)(h * CH) * DIM;
    const float* Wk = qkv_w + (size_t)(DIM + h * CH) * DIM;
    const float* Wv = qkv_w + (size_t)(2 * DIM + h * CH) * DIM;

    // --- norms: nq[c] = sqrt(Aq[c] . Wq[c]), nk likewise. 8 warps x 6 rows.
    for (int i = 0; i < 6; i++) {
        int r = w * 6 + i;
        float s = 0.f, s2 = 0.f;
        for (int k = lane; k < DIM; k += 32) {
            s  += Aq[r * DIM + k] * Wq[r * DIM + k];
            s2 += Ak[r * DIM + k] * Wk[r * DIM + k];
        }
#pragma unroll
        for (int o = 16; o; o >>= 1) {
            s  += __shfl_xor_sync(0xffffffffu, s, o);
            s2 += __shfl_xor_sync(0xffffffffu, s2, o);
        }
        if (lane == 0) { s_nq[r] = sqrtf(s); s_nk[r] = sqrtf(s2); }
    }

    // --- G = Aq @ Wk^T  (48x48, K=384), chunked K=64, transposed smem tiles
    float acc[3][3] = {};
    for (int k0 = 0; k0 < DIM; k0 += 64) {
        __syncthreads();
#pragma unroll
        for (int i = 0; i < 3; i++) {
            int idx = t + i * 256;
            int row = idx >> 4, c4 = (idx & 15) * 4;
            float4 va = *(const float4*)&Aq[(size_t)row * DIM + k0 + c4];
            float4 vb = *(const float4*)&Wk[(size_t)row * DIM + k0 + c4];
            sh0[(c4 + 0) * 50 + row] = va.x;  sh0[(c4 + 1) * 50 + row] = va.y;
            sh0[(c4 + 2) * 50 + row] = va.z;  sh0[(c4 + 3) * 50 + row] = va.w;
            sh1[(c4 + 0) * 50 + row] = vb.x;  sh1[(c4 + 1) * 50 + row] = vb.y;
            sh1[(c4 + 2) * 50 + row] = vb.z;  sh1[(c4 + 3) * 50 + row] = vb.w;
        }
        __syncthreads();
#pragma unroll 8
        for (int kk = 0; kk < 64; kk++) {
            float a0 = sh0[kk * 50 + ty * 3 + 0];
            float a1 = sh0[kk * 50 + ty * 3 + 1];
            float a2 = sh0[kk * 50 + ty * 3 + 2];
            float b0 = sh1[kk * 50 + tx * 3 + 0];
            float b1 = sh1[kk * 50 + tx * 3 + 1];
            float b2 = sh1[kk * 50 + tx * 3 + 2];
            acc[0][0] += a0 * b0; acc[0][1] += a0 * b1; acc[0][2] += a0 * b2;
            acc[1][0] += a1 * b0; acc[1][1] += a1 * b1; acc[1][2] += a1 * b2;
            acc[2][0] += a2 * b0; acc[2][1] += a2 * b1; acc[2][2] += a2 * b2;
        }
    }
#pragma unroll
    for (int i = 0; i < 3; i++)
#pragma unroll
        for (int j = 0; j < 3; j++)
            sG[(ty * 3 + i) * 48 + tx * 3 + j] = acc[i][j];
    __syncthreads();

    // --- softmax over d with normalization + temperature
    const float temp = temperature[h];
    const float EPS = 1e-12f;
    for (int i = 0; i < 6; i++) {
        int r = w * 6 + i;
        float inq = 1.f / fmaxf(s_nq[r], EPS);
        int d0 = lane, d1 = lane + 32;
        float l0 = sG[r * 48 + d0] * inq / fmaxf(s_nk[d0], EPS) * temp;
        float l1 = (d1 < 48) ? sG[r * 48 + d1] * inq / fmaxf(s_nk[d1], EPS) * temp
                             : -1e30f;
        float m = fmaxf(l0, l1);
#pragma unroll
        for (int o = 16; o; o >>= 1) m = fmaxf(m, __shfl_xor_sync(0xffffffffu, m, o));
        float e0 = expf(l0 - m);
        float e1 = (d1 < 48) ? expf(l1 - m) : 0.f;
        float s = e0 + e1;
#pragma unroll
        for (int o = 16; o; o >>= 1) s += __shfl_xor_sync(0xffffffffu, s, o);
        float inv = 1.f / s;
        sG[r * 48 + d0] = e0 * inv;
        if (d1 < 48) sG[r * 48 + d1] = e1 * inv;
    }
    __syncthreads();

    // --- M[c][j] = sum_d attn[c][d] * Wv[d][j]  (48x384), j-chunked 64
    float* Mout = g_M + ((size_t)b * DIM + h * CH) * DIM;
    for (int j0 = 0; j0 < DIM; j0 += 64) {
        __syncthreads();
#pragma unroll
        for (int i = 0; i < 3; i++) {
            int idx = t + i * 256;
            int row = idx >> 4, c4 = (idx & 15) * 4;
            *(float4*)&sh0[row * 64 + c4] =
                *(const float4*)&Wv[(size_t)row * DIM + j0 + c4];
        }
        __syncthreads();
        float4 a4[3];
#pragma unroll
        for (int i = 0; i < 3; i++) a4[i] = make_float4(0.f, 0.f, 0.f, 0.f);
        for (int d = 0; d < 48; d++) {
            float4 v = *(const float4*)&sh0[d * 64 + tx * 4];
#pragma unroll
            for (int i = 0; i < 3; i++) {
                float a = sG[(ty * 3 + i) * 48 + d];
                a4[i].x += a * v.x; a4[i].y += a * v.y;
                a4[i].z += a * v.z; a4[i].w += a * v.w;
            }
        }
#pragma unroll
        for (int i = 0; i < 3; i++)
            *(float4*)&Mout[(size_t)(ty * 3 + i) * DIM + j0 + tx * 4] = a4[i];
    }
}

// ---------------------------------------------------------------------------
extern "C" void kernel_launch(void* const* d_in, const int* in_sizes, int n_in,
                              void* d_out, int out_size) {
    const float *x = nullptr, *qkv_w = nullptr, *temp = nullptr,
                *proj_w = nullptr, *proj_b = nullptr;
    for (int i = 0; i < n_in; i++) {
        switch (in_sizes[i]) {
            case BATCH * NTOK * DIM: x      = (const float*)d_in[i]; break;
            case 3 * DIM * DIM:      qkv_w  = (const float*)d_in[i]; break;
            case HEADS:              temp   = (const float*)d_in[i]; break;
            case DIM * DIM:          proj_w = (const float*)d_in[i]; break;
            case DIM:                proj_b = (const float*)d_in[i]; break;
        }
    }
    float* out = (float*)d_out;

    float *pS, *pAqk, *pM, *pP;
    cudaGetSymbolAddress((void**)&pS,   g_S);
    cudaGetSymbolAddress((void**)&pAqk, g_Aqk);
    cudaGetSymbolAddress((void**)&pM,   g_M);
    cudaGetSymbolAddress((void**)&pP,   g_P);

    dim3 blk(256);
    // 1. S_b = X^T X  (upper-triangle tiles only: 21 per batch)
    k_syrk<<<dim3(21, 1, BATCH), blk>>>(x);
    // 2. Aqk = [Wq; Wk] @ S_b   (M = 768)
    k_gemm_nn<<<dim3(6, 12, BATCH), blk>>>(qkv_w, pS, pAqk, 768);
    // 3. attention core -> M_b
    k_attn<<<dim3(HEADS, BATCH), blk>>>(qkv_w, temp);
    // 4. P_b = proj_w @ M_b     (M = 384)
    k_gemm_nn<<<dim3(6, 6, BATCH), blk>>>(proj_w, pM, pP, DIM);
    // 5. out = X_b @ P_b^T + bias
    k_gemm_nt<<<dim3(6, 49, BATCH), blk>>>(x, pP, proj_b, out);
}

// round 5
// speedup vs baseline: 2.5896x; 2.4601x over previous
#include <cuda_runtime.h>
#include <cuda_bf16.h>
#include <math.h>
#include <stdint.h>
#include <limits.h>

#define BATCH 32
#define NTOK  3136
#define DIM   384
#define HEADS 8
#define CH    48
#define QKROWS 768

// ---------------- scratch (device globals; no allocs allowed) ----------------
__device__ unsigned short g_Xh [(size_t)BATCH*NTOK*DIM];  // X  [n][d] bf16 hi
__device__ unsigned short g_Xl [(size_t)BATCH*NTOK*DIM];  // X  [n][d] bf16 lo
__device__ unsigned short g_Xth[(size_t)BATCH*NTOK*DIM];  // Xt [d][n] bf16 hi
__device__ unsigned short g_Xtl[(size_t)BATCH*NTOK*DIM];  // Xt [d][n] bf16 lo
__device__ unsigned short g_Sh [(size_t)BATCH*DIM*DIM];   // S = X^T X
__device__ unsigned short g_Sl [(size_t)BATCH*DIM*DIM];
__device__ float          g_Aqk[(size_t)BATCH*QKROWS*DIM];// [Wq;Wk] @ S (fp32)
__device__ float          g_M  [(size_t)BATCH*DIM*DIM];   // attn @ Wv (fp32)
__device__ unsigned short g_Mth[(size_t)BATCH*DIM*DIM];   // M^T hi
__device__ unsigned short g_Mtl[(size_t)BATCH*DIM*DIM];   // M^T lo
__device__ unsigned short g_Ph [(size_t)BATCH*DIM*DIM];   // P = proj_w @ M
__device__ unsigned short g_Pl [(size_t)BATCH*DIM*DIM];
__device__ unsigned short g_Wqh[(size_t)QKROWS*DIM];
__device__ unsigned short g_Wql[(size_t)QKROWS*DIM];
__device__ unsigned short g_Pwh[(size_t)DIM*DIM];
__device__ unsigned short g_Pwl[(size_t)DIM*DIM];

// ---------------- helpers ----------------
__device__ __forceinline__ uint32_t su32(const void* p) {
    uint32_t a;
    asm("{ .reg .u64 t; cvta.to.shared.u64 t, %1; cvt.u32.u64 %0, t; }"
        : "=r"(a) : "l"(p));
    return a;
}

#define LDSM4(R0, R1, R2, R3, ADDR)                                            \
    asm volatile("ldmatrix.sync.aligned.m8n8.x4.shared.b16 {%0,%1,%2,%3}, [%4];" \
                 : "=r"(R0), "=r"(R1), "=r"(R2), "=r"(R3) : "r"(ADDR))

#define MMA16816(ACC, A, B0, B1)                                               \
    asm volatile("mma.sync.aligned.m16n8k16.row.col.f32.bf16.bf16.f32 "        \
                 "{%0,%1,%2,%3}, {%4,%5,%6,%7}, {%8,%9}, {%0,%1,%2,%3};"       \
                 : "+f"((ACC)[0]), "+f"((ACC)[1]), "+f"((ACC)[2]), "+f"((ACC)[3]) \
                 : "r"((A)[0]), "r"((A)[1]), "r"((A)[2]), "r"((A)[3]),         \
                   "r"(B0), "r"(B1))

__device__ __forceinline__ void cp16(uint32_t d, const void* g) {
    asm volatile("cp.async.cg.shared.global [%0], [%1], 16;" :: "r"(d), "l"(g));
}

__device__ __forceinline__ void split4(const float f[4], uint2& h2, uint2& l2) {
    unsigned short hs[4], ls[4];
#pragma unroll
    for (int j = 0; j < 4; j++) {
        __nv_bfloat16 hb = __float2bfloat16(f[j]);
        float rem = f[j] - __bfloat162float(hb);
        __nv_bfloat16 lb = __float2bfloat16(rem);
        hs[j] = __bfloat16_as_ushort(hb);
        ls[j] = __bfloat16_as_ushort(lb);
    }
    h2.x = (uint32_t)hs[0] | ((uint32_t)hs[1] << 16);
    h2.y = (uint32_t)hs[2] | ((uint32_t)hs[3] << 16);
    l2.x = (uint32_t)ls[0] | ((uint32_t)ls[1] << 16);
    l2.y = (uint32_t)ls[2] | ((uint32_t)ls[3] << 16);
}

// ---------------------------------------------------------------------------
// conv: X fp32 -> Xh/Xl [n][d] and Xth/Xtl [d][n] (32x32 transpose tiles)
// ---------------------------------------------------------------------------
__global__ __launch_bounds__(256) void k_conv_x(const float* __restrict__ x) {
    __shared__ float s[32][33];
    const int b = blockIdx.z, n0 = blockIdx.x * 32, d0 = blockIdx.y * 32;
    const int t = threadIdx.x, r = t >> 3, c4 = (t & 7) * 4;
    const size_t xb = (size_t)b * NTOK * DIM;

    float4 v = *(const float4*)&x[xb + (size_t)(n0 + r) * DIM + d0 + c4];
    float f[4] = {v.x, v.y, v.z, v.w};
    uint2 h2, l2;
    split4(f, h2, l2);
    *(uint2*)&g_Xh[xb + (size_t)(n0 + r) * DIM + d0 + c4] = h2;
    *(uint2*)&g_Xl[xb + (size_t)(n0 + r) * DIM + d0 + c4] = l2;
    s[r][c4 + 0] = v.x; s[r][c4 + 1] = v.y; s[r][c4 + 2] = v.z; s[r][c4 + 3] = v.w;
    __syncthreads();
    float g[4];
#pragma unroll
    for (int j = 0; j < 4; j++) g[j] = s[c4 + j][r];
    split4(g, h2, l2);
    *(uint2*)&g_Xth[xb + (size_t)(d0 + r) * NTOK + n0 + c4] = h2;
    *(uint2*)&g_Xtl[xb + (size_t)(d0 + r) * NTOK + n0 + c4] = l2;
}

__global__ __launch_bounds__(256) void k_split(const float* __restrict__ src,
                                               unsigned short* __restrict__ h,
                                               unsigned short* __restrict__ l, int n4) {
    int i = blockIdx.x * 256 + threadIdx.x;
    if (i >= n4) return;
    float4 v = ((const float4*)src)[i];
    float f[4] = {v.x, v.y, v.z, v.w};
    uint2 h2, l2;
    split4(f, h2, l2);
    ((uint2*)h)[i] = h2;
    ((uint2*)l)[i] = l2;
}

// transpose + split: M[b] (DIMxDIM fp32) -> Mt hi/lo
__global__ __launch_bounds__(256) void k_tsplit(const float* __restrict__ src,
                                                unsigned short* __restrict__ dh,
                                                unsigned short* __restrict__ dl) {
    __shared__ float s[32][33];
    const int b = blockIdx.z, r0 = blockIdx.x * 32, c0 = blockIdx.y * 32;
    const float* S = src + (size_t)b * DIM * DIM;
    const int t = threadIdx.x, r = t >> 3, c4 = (t & 7) * 4;
    float4 v = *(const float4*)&S[(size_t)(r0 + r) * DIM + c0 + c4];
    s[r][c4 + 0] = v.x; s[r][c4 + 1] = v.y; s[r][c4 + 2] = v.z; s[r][c4 + 3] = v.w;
    __syncthreads();
    float g[4];
#pragma unroll
    for (int j = 0; j < 4; j++) g[j] = s[c4 + j][r];
    uint2 h2, l2;
    split4(g, h2, l2);
    size_t o = (size_t)b * DIM * DIM + (size_t)(c0 + r) * DIM + r0 + c4;
    *(uint2*)&dh[o] = h2;
    *(uint2*)&dl[o] = l2;
}

// ---------------------------------------------------------------------------
// HMMA split-bf16 GEMM: D[b][m][n] = sum_k (Ah+Al)[m][k]*(Bh+Bl)[n][k]
// (AlBl dropped). 128x128 CTA tile, BK=64, cp.async double buffer,
// 8 warps as 4(M)x2(N), warp tile 32x64, mma.sync m16n8k16 bf16.
// smem tile layout: rows of 128B (64 bf16), 16B chunk c swizzled c^(r&7).
// ---------------------------------------------------------------------------
__device__ __forceinline__ void issue_chunk(
    uint32_t su, int c, int tid,
    const unsigned short* const* src, const int* row0, const int* lds, const int* clmp)
{
    const uint32_t sbuf = su + (uint32_t)(c & 1) * 65536u;
#pragma unroll
    for (int T = 0; T < 4; T++) {
#pragma unroll
        for (int s = 0; s < 4; s++) {
            int idx = tid + s * 256;
            int r = idx >> 3, cc = idx & 7;
            int rg = min(row0[T] + r, clmp[T]);
            const void* g = src[T] + (size_t)rg * lds[T] + c * 64 + cc * 8;
            uint32_t d = sbuf + (uint32_t)T * 16384u
                       + (uint32_t)(r * 128 + ((cc ^ (r & 7)) << 4));
            cp16(d, g);
        }
    }
    asm volatile("cp.async.commit_group;");
}

__global__ __launch_bounds__(256, 1)
void k_gemm_mma(const unsigned short* __restrict__ AhP, const unsigned short* __restrict__ AlP,
                const unsigned short* __restrict__ BhP, const unsigned short* __restrict__ BlP,
                size_t sA, size_t sB, int lda, int ldb, int K, int Mtot,
                float* __restrict__ Cf, unsigned short* __restrict__ ChP,
                unsigned short* __restrict__ ClP, const float* __restrict__ bias,
                size_t sC, int ldc)
{
    extern __shared__ __align__(16) char dsm[];
    const int tid = threadIdx.x, warp = tid >> 5, lane = tid & 31;
    const int b = blockIdx.z;
    const int n0 = blockIdx.x * 128, m0 = blockIdx.y * 128;
    const uint32_t su = su32(dsm);

    const unsigned short* src[4] = {AhP + (size_t)b * sA, AlP + (size_t)b * sA,
                                    BhP + (size_t)b * sB, BlP + (size_t)b * sB};
    const int row0[4] = {m0, m0, n0, n0};
    const int lds[4]  = {lda, lda, ldb, ldb};
    const int clmp[4] = {Mtot - 1, Mtot - 1, INT_MAX, INT_MAX};
    const int C = K >> 6;

    const int wm = warp >> 1, wn = warp & 1;

    float acc[2][8][4];
#pragma unroll
    for (int i = 0; i < 2; i++)
#pragma unroll
        for (int j = 0; j < 8; j++)
#pragma unroll
            for (int q = 0; q < 4; q++) acc[i][j][q] = 0.f;

    issue_chunk(su, 0, tid, src, row0, lds, clmp);

    for (int c = 0; c < C; c++) {
        if (c + 1 < C) {
            issue_chunk(su, c + 1, tid, src, row0, lds, clmp);
            asm volatile("cp.async.wait_group 1;");
        } else {
            asm volatile("cp.async.wait_group 0;");
        }
        __syncthreads();
        const uint32_t sbuf = su + (uint32_t)(c & 1) * 65536u;

#pragma unroll
        for (int kb = 0; kb < 4; kb++) {
            uint32_t ah[2][4], al[2][4], bh[4][4], bl[4][4];
#pragma unroll
            for (int ai = 0; ai < 2; ai++) {
                int r = wm * 32 + ai * 16 + (lane & 15);
                int cch = kb * 2 + (lane >> 4);
                uint32_t off = (uint32_t)(r * 128 + ((cch ^ (r & 7)) << 4));
                LDSM4(ah[ai][0], ah[ai][1], ah[ai][2], ah[ai][3], sbuf + off);
                LDSM4(al[ai][0], al[ai][1], al[ai][2], al[ai][3], sbuf + 16384u + off);
            }
#pragma unroll
            for (int g = 0; g < 4; g++) {
                int r = wn * 64 + g * 16 + (lane & 7) + ((lane >> 4) << 3);
                int cch = kb * 2 + ((lane >> 3) & 1);
                uint32_t off = (uint32_t)(r * 128 + ((cch ^ (r & 7)) << 4));
                LDSM4(bh[g][0], bh[g][1], bh[g][2], bh[g][3], sbuf + 32768u + off);
                LDSM4(bl[g][0], bl[g][1], bl[g][2], bl[g][3], sbuf + 49152u + off);
            }
#pragma unroll
            for (int ai = 0; ai < 2; ai++)
#pragma unroll
                for (int ni = 0; ni < 8; ni++) {
                    int g = ni >> 1, hv = (ni & 1) * 2;
                    MMA16816(acc[ai][ni], ah[ai], bh[g][hv], bh[g][hv + 1]);
                    MMA16816(acc[ai][ni], ah[ai], bl[g][hv], bl[g][hv + 1]);
                    MMA16816(acc[ai][ni], al[ai], bh[g][hv], bh[g][hv + 1]);
                }
        }
        __syncthreads();
    }

    // ---------------- epilogue (direct from accumulators) ----------------
    const int gq = lane >> 2, tg = lane & 3;
    if (Cf) {
        float* Cb = Cf + (size_t)b * sC;
#pragma unroll
        for (int ai = 0; ai < 2; ai++)
#pragma unroll
            for (int ni = 0; ni < 8; ni++) {
                int rb = m0 + wm * 32 + ai * 16 + gq;
                int col = n0 + wn * 64 + ni * 8 + tg * 2;
                float bx = 0.f, by = 0.f;
                if (bias) { float2 bv = *(const float2*)&bias[col]; bx = bv.x; by = bv.y; }
                if (rb < Mtot) {
                    float2 o = {acc[ai][ni][0] + bx, acc[ai][ni][1] + by};
                    *(float2*)&Cb[(size_t)rb * ldc + col] = o;
                }
                if (rb + 8 < Mtot) {
                    float2 o = {acc[ai][ni][2] + bx, acc[ai][ni][3] + by};
                    *(float2*)&Cb[(size_t)(rb + 8) * ldc + col] = o;
                }
            }
    } else {
        unsigned short* ChB = ChP + (size_t)b * sC;
        unsigned short* ClB = ClP + (size_t)b * sC;
#pragma unroll
        for (int ai = 0; ai < 2; ai++)
#pragma unroll
            for (int ni = 0; ni < 8; ni++) {
                int rb = m0 + wm * 32 + ai * 16 + gq;
                int col = n0 + wn * 64 + ni * 8 + tg * 2;
#pragma unroll
                for (int hrow = 0; hrow < 2; hrow++) {
                    int r = rb + hrow * 8;
                    if (r >= Mtot) continue;
                    float v0 = acc[ai][ni][hrow * 2 + 0];
                    float v1 = acc[ai][ni][hrow * 2 + 1];
                    __nv_bfloat16 h0 = __float2bfloat16(v0);
                    __nv_bfloat16 h1 = __float2bfloat16(v1);
                    __nv_bfloat16 l0 = __float2bfloat16(v0 - __bfloat162float(h0));
                    __nv_bfloat16 l1 = __float2bfloat16(v1 - __bfloat162float(h1));
                    uint32_t hp = (uint32_t)__bfloat16_as_ushort(h0)
                                | ((uint32_t)__bfloat16_as_ushort(h1) << 16);
                    uint32_t lp = (uint32_t)__bfloat16_as_ushort(l0)
                                | ((uint32_t)__bfloat16_as_ushort(l1) << 16);
                    *(uint32_t*)&ChB[(size_t)r * ldc + col] = hp;
                    *(uint32_t*)&ClB[(size_t)r * ldc + col] = lp;
                }
            }
    }
}

// ---------------------------------------------------------------------------
// Attention core per (b,h): norms, Gram, softmax, M = attn @ Wv_h (fp32)
// ---------------------------------------------------------------------------
__global__ __launch_bounds__(256) void k_attn(const float* __restrict__ qkv_w,
                                              const float* __restrict__ temperature) {
    const int b = blockIdx.y;
    const int h = blockIdx.x;
    const int t = threadIdx.x;
    const int lane = t & 31, w = t >> 5;
    const int ty = t >> 4, tx = t & 15;

    __shared__ __align__(16) float sh0[64 * 50];
    __shared__ __align__(16) float sh1[64 * 50];
    __shared__ float sG[48 * 48];
    __shared__ float s_nq[48], s_nk[48];

    const float* Aq = g_Aqk + ((size_t)b * QKROWS + h * CH) * DIM;
    const float* Ak = Aq + (size_t)DIM * DIM;
    const float* Wq = qkv_w + (size_t)(h * CH) * DIM;
    const float* Wk = qkv_w + (size_t)(DIM + h * CH) * DIM;
    const float* Wv = qkv_w + (size_t)(2 * DIM + h * CH) * DIM;

    for (int i = 0; i < 6; i++) {
        int r = w * 6 + i;
        float s = 0.f, s2 = 0.f;
        for (int k = lane; k < DIM; k += 32) {
            s  += Aq[r * DIM + k] * Wq[r * DIM + k];
            s2 += Ak[r * DIM + k] * Wk[r * DIM + k];
        }
#pragma unroll
        for (int o = 16; o; o >>= 1) {
            s  += __shfl_xor_sync(0xffffffffu, s, o);
            s2 += __shfl_xor_sync(0xffffffffu, s2, o);
        }
        if (lane == 0) { s_nq[r] = sqrtf(s); s_nk[r] = sqrtf(s2); }
    }

    float acc[3][3] = {};
    for (int k0 = 0; k0 < DIM; k0 += 64) {
        __syncthreads();
#pragma unroll
        for (int i = 0; i < 3; i++) {
            int idx = t + i * 256;
            int row = idx >> 4, c4 = (idx & 15) * 4;
            float4 va = *(const float4*)&Aq[(size_t)row * DIM + k0 + c4];
            float4 vb = *(const float4*)&Wk[(size_t)row * DIM + k0 + c4];
            sh0[(c4 + 0) * 50 + row] = va.x;  sh0[(c4 + 1) * 50 + row] = va.y;
            sh0[(c4 + 2) * 50 + row] = va.z;  sh0[(c4 + 3) * 50 + row] = va.w;
            sh1[(c4 + 0) * 50 + row] = vb.x;  sh1[(c4 + 1) * 50 + row] = vb.y;
            sh1[(c4 + 2) * 50 + row] = vb.z;  sh1[(c4 + 3) * 50 + row] = vb.w;
        }
        __syncthreads();
#pragma unroll 8
        for (int kk = 0; kk < 64; kk++) {
            float a0 = sh0[kk * 50 + ty * 3 + 0];
            float a1 = sh0[kk * 50 + ty * 3 + 1];
            float a2 = sh0[kk * 50 + ty * 3 + 2];
            float b0 = sh1[kk * 50 + tx * 3 + 0];
            float b1 = sh1[kk * 50 + tx * 3 + 1];
            float b2 = sh1[kk * 50 + tx * 3 + 2];
            acc[0][0] += a0 * b0; acc[0][1] += a0 * b1; acc[0][2] += a0 * b2;
            acc[1][0] += a1 * b0; acc[1][1] += a1 * b1; acc[1][2] += a1 * b2;
            acc[2][0] += a2 * b0; acc[2][1] += a2 * b1; acc[2][2] += a2 * b2;
        }
    }
#pragma unroll
    for (int i = 0; i < 3; i++)
#pragma unroll
        for (int j = 0; j < 3; j++)
            sG[(ty * 3 + i) * 48 + tx * 3 + j] = acc[i][j];
    __syncthreads();

    const float temp = temperature[h];
    const float EPS = 1e-12f;
    for (int i = 0; i < 6; i++) {
        int r = w * 6 + i;
        float inq = 1.f / fmaxf(s_nq[r], EPS);
        int d0 = lane, d1 = lane + 32;
        float l0 = sG[r * 48 + d0] * inq / fmaxf(s_nk[d0], EPS) * temp;
        float l1 = (d1 < 48) ? sG[r * 48 + d1] * inq / fmaxf(s_nk[d1], EPS) * temp
                             : -1e30f;
        float m = fmaxf(l0, l1);
#pragma unroll
        for (int o = 16; o; o >>= 1) m = fmaxf(m, __shfl_xor_sync(0xffffffffu, m, o));
        float e0 = expf(l0 - m);
        float e1 = (d1 < 48) ? expf(l1 - m) : 0.f;
        float s = e0 + e1;
#pragma unroll
        for (int o = 16; o; o >>= 1) s += __shfl_xor_sync(0xffffffffu, s, o);
        float inv = 1.f / s;
        sG[r * 48 + d0] = e0 * inv;
        if (d1 < 48) sG[r * 48 + d1] = e1 * inv;
    }
    __syncthreads();

    float* Mout = g_M + ((size_t)b * DIM + h * CH) * DIM;
    for (int j0 = 0; j0 < DIM; j0 += 64) {
        __syncthreads();
#pragma unroll
        for (int i = 0; i < 3; i++) {
            int idx = t + i * 256;
            int row = idx >> 4, c4 = (idx & 15) * 4;
            *(float4*)&sh0[row * 64 + c4] =
                *(const float4*)&Wv[(size_t)row * DIM + j0 + c4];
        }
        __syncthreads();
        float4 a4[3];
#pragma unroll
        for (int i = 0; i < 3; i++) a4[i] = make_float4(0.f, 0.f, 0.f, 0.f);
        for (int d = 0; d < 48; d++) {
            float4 v = *(const float4*)&sh0[d * 64 + tx * 4];
#pragma unroll
            for (int i = 0; i < 3; i++) {
                float a = sG[(ty * 3 + i) * 48 + d];
                a4[i].x += a * v.x; a4[i].y += a * v.y;
                a4[i].z += a * v.z; a4[i].w += a * v.w;
            }
        }
#pragma unroll
        for (int i = 0; i < 3; i++)
            *(float4*)&Mout[(size_t)(ty * 3 + i) * DIM + j0 + tx * 4] = a4[i];
    }
}

// ---------------------------------------------------------------------------
#define SMEM_DYN (131072)

extern "C" void kernel_launch(void* const* d_in, const int* in_sizes, int n_in,
                              void* d_out, int out_size) {
    const float *x = nullptr, *qkv_w = nullptr, *temp = nullptr,
                *proj_w = nullptr, *proj_b = nullptr;
    for (int i = 0; i < n_in; i++) {
        switch (in_sizes[i]) {
            case BATCH * NTOK * DIM: x      = (const float*)d_in[i]; break;
            case 3 * DIM * DIM:      qkv_w  = (const float*)d_in[i]; break;
            case HEADS:              temp   = (const float*)d_in[i]; break;
            case DIM * DIM:          proj_w = (const float*)d_in[i]; break;
            case DIM:                proj_b = (const float*)d_in[i]; break;
        }
    }
    float* out = (float*)d_out;

    unsigned short *pXh, *pXl, *pXth, *pXtl, *pSh, *pSl, *pMth, *pMtl,
                   *pPh, *pPl, *pWqh, *pWql, *pPwh, *pPwl;
    float *pAqk, *pM;
    cudaGetSymbolAddress((void**)&pXh,  g_Xh);
    cudaGetSymbolAddress((void**)&pXl,  g_Xl);
    cudaGetSymbolAddress((void**)&pXth, g_Xth);
    cudaGetSymbolAddress((void**)&pXtl, g_Xtl);
    cudaGetSymbolAddress((void**)&pSh,  g_Sh);
    cudaGetSymbolAddress((void**)&pSl,  g_Sl);
    cudaGetSymbolAddress((void**)&pAqk, g_Aqk);
    cudaGetSymbolAddress((void**)&pM,   g_M);
    cudaGetSymbolAddress((void**)&pMth, g_Mth);
    cudaGetSymbolAddress((void**)&pMtl, g_Mtl);
    cudaGetSymbolAddress((void**)&pPh,  g_Ph);
    cudaGetSymbolAddress((void**)&pPl,  g_Pl);
    cudaGetSymbolAddress((void**)&pWqh, g_Wqh);
    cudaGetSymbolAddress((void**)&pWql, g_Wql);
    cudaGetSymbolAddress((void**)&pPwh, g_Pwh);
    cudaGetSymbolAddress((void**)&pPwl, g_Pwl);

    cudaFuncSetAttribute(k_gemm_mma, cudaFuncAttributeMaxDynamicSharedMemorySize, SMEM_DYN);

    // 0. conversions
    k_conv_x<<<dim3(NTOK / 32, DIM / 32, BATCH), 256>>>(x);
    k_split<<<(QKROWS * DIM / 4 + 255) / 256, 256>>>(qkv_w, pWqh, pWql, QKROWS * DIM / 4);
    k_split<<<(DIM * DIM / 4 + 255) / 256, 256>>>(proj_w, pPwh, pPwl, DIM * DIM / 4);

    // 1. S_b = X^T X  (A=B=Xt, K=NTOK), out bf16 split
    k_gemm_mma<<<dim3(3, 3, BATCH), 256, SMEM_DYN>>>(
        pXth, pXtl, pXth, pXtl,
        (size_t)NTOK * DIM, (size_t)NTOK * DIM, NTOK, NTOK, NTOK, DIM,
        nullptr, pSh, pSl, nullptr, (size_t)DIM * DIM, DIM);

    // 2. Aqk = [Wq;Wk] @ S_b  (S symmetric), out fp32
    k_gemm_mma<<<dim3(3, 6, BATCH), 256, SMEM_DYN>>>(
        pWqh, pWql, pSh, pSl,
        (size_t)0, (size_t)DIM * DIM, DIM, DIM, DIM, QKROWS,
        pAqk, nullptr, nullptr, nullptr, (size_t)QKROWS * DIM, DIM);

    // 3. attention core -> M (fp32), then transpose+split
    k_attn<<<dim3(HEADS, BATCH), 256>>>(qkv_w, temp);
    k_tsplit<<<dim3(12, 12, BATCH), 256>>>(pM, pMth, pMtl);

    // 4. P_b = proj_w @ M_b, out bf16 split
    k_gemm_mma<<<dim3(3, 3, BATCH), 256, SMEM_DYN>>>(
        pPwh, pPwl, pMth, pMtl,
        (size_t)0, (size_t)DIM * DIM, DIM, DIM, DIM, DIM,
        nullptr, pPh, pPl, nullptr, (size_t)DIM * DIM, DIM);

    // 5. out = X_b @ P_b^T + bias, out fp32
    k_gemm_mma<<<dim3(3, 25, BATCH), 256, SMEM_DYN>>>(
        pXh, pXl, pPh, pPl,
        (size_t)NTOK * DIM, (size_t)DIM * DIM, DIM, DIM, DIM, NTOK,
        out, nullptr, nullptr, proj_b, (size_t)NTOK * DIM, DIM);
}